// round 12
// baseline (speedup 1.0000x reference)
#include <cuda_runtime.h>
#include <cuda_fp16.h>
#include <cstdint>

// ---------------------------------------------------------------------------
// BitLinear: out[m,n] = scale[n] * sum_k xh[m,k] * wq[n,k]
//   xh = fp16(x) [8192,2048], wq = ternary fp16 [8192,2048], out fp32.
//
// GEMM: mma.sync.m16n8k16.f32, CTA 128x128 with 4 warps (warp tile 64x64 ->
// minimal crossbar traffic), BK=64, 3-stage cp.async, 2 CTAs/SM.
// NEW: double-buffered ldmatrix fragment registers — LDSM for ks+1 issues
// before the MMA block of ks, overlapping smem reads with tensor work
// (R11 ncu: tensor pipe 62% busy, 38% idle on LDSM dependency stalls).
// Register budget: 128 thr/CTA, 2 CTAs -> ~250 regs/thread available.
// ---------------------------------------------------------------------------

#define M_TOT 8192
#define N_TOT 8192
#define K_TOT 2048

#define BM 128
#define BN 128
#define BK 64
#define STAGES 3
#define NUM_CHUNKS (K_TOT / BK)      // 32

// smem row: 64 halves + 8 pad = 144 bytes (9 x 16B granules, odd -> no conflicts)
#define SROWB 144
#define STILE_BYTES (BM * SROWB)     // 18432
#define SMEM_A_OFF(s) ((s) * STILE_BYTES)
#define SMEM_B_OFF(s) (STAGES * STILE_BYTES + (s) * STILE_BYTES)
#define SMEM_TOTAL (2 * STAGES * STILE_BYTES)   // 110592 -> 2 CTAs/SM

__device__ __half g_Xh[(size_t)M_TOT * K_TOT];
__device__ __half g_Wq[(size_t)N_TOT * K_TOT];
__device__ float  g_scale[N_TOT];

// ------------------------------ helpers ------------------------------------
__device__ __forceinline__ uint32_t smem_u32(const void* p) {
    uint32_t a;
    asm("{ .reg .u64 t; cvta.to.shared.u64 t, %1; cvt.u32.u64 %0, t; }"
        : "=r"(a) : "l"(p));
    return a;
}

__device__ __forceinline__ void cp_async16(uint32_t dst, const void* src) {
    asm volatile("cp.async.cg.shared.global [%0], [%1], 16;"
                 :: "r"(dst), "l"(src));
}

__device__ __forceinline__ void ldsm_x4(uint32_t addr, uint32_t* r) {
    asm volatile("ldmatrix.sync.aligned.m8n8.x4.shared.b16 {%0,%1,%2,%3}, [%4];"
                 : "=r"(r[0]), "=r"(r[1]), "=r"(r[2]), "=r"(r[3]) : "r"(addr));
}

__device__ __forceinline__ void mma16816(float* c, const uint32_t* a,
                                         uint32_t b0, uint32_t b1) {
    asm volatile(
        "mma.sync.aligned.m16n8k16.row.col.f32.f16.f16.f32 "
        "{%0,%1,%2,%3}, {%4,%5,%6,%7}, {%8,%9}, {%0,%1,%2,%3};"
        : "+f"(c[0]), "+f"(c[1]), "+f"(c[2]), "+f"(c[3])
        : "r"(a[0]), "r"(a[1]), "r"(a[2]), "r"(a[3]), "r"(b0), "r"(b1));
}

// ------------------------------ fused prep kernel --------------------------
// blocks [0, 8192): quantize W row b  -> g_Wq, g_scale
// blocks [8192, 16384): convert x slice -> g_Xh
__global__ void prep_kernel(const float* __restrict__ x,
                            const float* __restrict__ W) {
    const int b   = blockIdx.x;
    const int tid = threadIdx.x;

    if (b < N_TOT) {
        const float* wr = W + (size_t)b * K_TOT;
        const int base = tid * 8;
        float4 a = *reinterpret_cast<const float4*>(wr + base);
        float4 c = *reinterpret_cast<const float4*>(wr + base + 4);
        float s = fabsf(a.x) + fabsf(a.y) + fabsf(a.z) + fabsf(a.w) +
                  fabsf(c.x) + fabsf(c.y) + fabsf(c.z) + fabsf(c.w);
        #pragma unroll
        for (int o = 16; o; o >>= 1) s += __shfl_xor_sync(0xFFFFFFFFu, s, o);

        __shared__ float warp_s[8];
        __shared__ float s_scale;
        if ((tid & 31) == 0) warp_s[tid >> 5] = s;
        __syncthreads();
        if (tid == 0) {
            float t = 0.f;
            #pragma unroll
            for (int i = 0; i < 8; i++) t += warp_s[i];
            float sc = t * (1.0f / 2048.0f);
            if (sc < 1e-5f) sc = 1e-5f;
            g_scale[b] = sc;
            s_scale = sc;
        }
        __syncthreads();
        const float sc = s_scale;

        float v[8] = {a.x, a.y, a.z, a.w, c.x, c.y, c.z, c.w};
        __half q[8];
        #pragma unroll
        for (int i = 0; i < 8; i++) {
            float t = rintf(v[i] / sc);          // matches jnp.round
            t = fmaxf(-1.f, fminf(1.f, t));
            q[i] = __float2half_rn(t);
        }
        *reinterpret_cast<uint4*>(g_Wq + (size_t)b * K_TOT + base) =
            *reinterpret_cast<uint4*>(q);
    } else {
        size_t i = (size_t)(b - N_TOT) * 256 + tid;
        const float4* X4 = reinterpret_cast<const float4*>(x);
        float4 a = X4[2 * i];
        float4 c = X4[2 * i + 1];
        __half2 h0 = __floats2half2_rn(a.x, a.y);
        __half2 h1 = __floats2half2_rn(a.z, a.w);
        __half2 h2 = __floats2half2_rn(c.x, c.y);
        __half2 h3 = __floats2half2_rn(c.z, c.w);
        uint4 o;
        o.x = *reinterpret_cast<uint32_t*>(&h0);
        o.y = *reinterpret_cast<uint32_t*>(&h1);
        o.z = *reinterpret_cast<uint32_t*>(&h2);
        o.w = *reinterpret_cast<uint32_t*>(&h3);
        reinterpret_cast<uint4*>(g_Xh)[i] = o;
    }
}

// ------------------------------ GEMM kernel --------------------------------
__global__ void __launch_bounds__(128, 2)
bitlinear_gemm(float* __restrict__ out) {
    extern __shared__ char smem[];
    const uint32_t sbase = smem_u32(smem);
    const int tid    = threadIdx.x;
    const int wid    = tid >> 5;
    const int lane   = tid & 31;
    const int warp_m = wid & 1;       // 2 warps along M (64 each)
    const int warp_n = wid >> 1;      // 2 warps along N (64 each)
    const int m0 = blockIdx.y * BM;
    const int n0 = blockIdx.x * BN;

    const __half* Ag = g_Xh + (size_t)m0 * K_TOT;
    const __half* Bg = g_Wq + (size_t)n0 * K_TOT;

    // copy: A/B each 128 rows x 8 segs(16B) = 1024 segs; 8/thread
    auto issue_copy = [&](int stage, int chunk) {
        const int k0 = chunk * BK;
        uint32_t da = sbase + SMEM_A_OFF(stage);
        uint32_t db = sbase + SMEM_B_OFF(stage);
        #pragma unroll
        for (int j = 0; j < 8; j++) {
            int s = tid + 128 * j;
            int row = s >> 3, sg = s & 7;
            uint32_t off = row * SROWB + sg * 16;
            cp_async16(da + off, Ag + (size_t)row * K_TOT + k0 + sg * 8);
            cp_async16(db + off, Bg + (size_t)row * K_TOT + k0 + sg * 8);
        }
    };

    // ldmatrix per-thread address components
    const int aRow = warp_m * 64 + (lane & 15);        // + mt*16
    const int aCol = (lane >> 4) * 8;                  // + ks*16
    const int g    = lane >> 3;
    const int bRow = warp_n * 64 + ((g >> 1) << 3) + (lane & 7);  // + nt*16
    const int bCol = (g & 1) * 8;                      // + ks*16

    float acc[4][8][4];
    #pragma unroll
    for (int i = 0; i < 4; i++)
        #pragma unroll
        for (int j = 0; j < 8; j++)
            #pragma unroll
            for (int t = 0; t < 4; t++) acc[i][j][t] = 0.f;

    // double-buffered fragment registers
    uint32_t af[2][4][4];
    uint32_t bf[2][4][4];

    auto load_frags = [&](uint32_t sa, uint32_t sb, int ks, int buf) {
        #pragma unroll
        for (int mt = 0; mt < 4; mt++)
            ldsm_x4(sa + (aRow + mt * 16) * SROWB + (aCol + ks * 16) * 2,
                    af[buf][mt]);
        #pragma unroll
        for (int nt = 0; nt < 4; nt++)
            ldsm_x4(sb + (bRow + nt * 16) * SROWB + (bCol + ks * 16) * 2,
                    bf[buf][nt]);
    };
    auto do_mma = [&](int buf) {
        #pragma unroll
        for (int mi = 0; mi < 4; mi++)
            #pragma unroll
            for (int ni = 0; ni < 8; ni++)
                mma16816(acc[mi][ni], af[buf][mi],
                         bf[buf][ni >> 1][(ni & 1) * 2],
                         bf[buf][ni >> 1][(ni & 1) * 2 + 1]);
    };

    // prologue: stages 0..1
    issue_copy(0, 0);
    asm volatile("cp.async.commit_group;");
    issue_copy(1, 1);
    asm volatile("cp.async.commit_group;");

    for (int c = 0; c < NUM_CHUNKS; c++) {
        asm volatile("cp.async.wait_group %0;" :: "n"(STAGES - 2));
        __syncthreads();

        const int nc = c + STAGES - 1;
        if (nc < NUM_CHUNKS) issue_copy(nc % STAGES, nc);
        asm volatile("cp.async.commit_group;");

        const int st = c % STAGES;
        const uint32_t sa = sbase + SMEM_A_OFF(st);
        const uint32_t sb = sbase + SMEM_B_OFF(st);

        // software-pipelined ks loop: LDSM(ks+1) issued before MMA(ks)
        load_frags(sa, sb, 0, 0);
        #pragma unroll
        for (int ks = 0; ks < 4; ks++) {
            const int cur = ks & 1;
            if (ks < 3) load_frags(sa, sb, ks + 1, cur ^ 1);
            do_mma(cur);
        }
    }

    // ---------------- epilogue: scale by g_scale[n], store fp32 ------------
    const int q = lane >> 2;          // row-in-8
    const int t = lane & 3;           // col-pair
    #pragma unroll
    for (int ni = 0; ni < 8; ni++) {
        const int n = n0 + warp_n * 64 + ni * 8 + t * 2;
        const float2 sc = *reinterpret_cast<const float2*>(&g_scale[n]);
        #pragma unroll
        for (int mi = 0; mi < 4; mi++) {
            const int m = m0 + warp_m * 64 + mi * 16 + q;
            float2 v0 = make_float2(acc[mi][ni][0] * sc.x, acc[mi][ni][1] * sc.y);
            float2 v1 = make_float2(acc[mi][ni][2] * sc.x, acc[mi][ni][3] * sc.y);
            *reinterpret_cast<float2*>(out + (size_t)m * N_TOT + n) = v0;
            *reinterpret_cast<float2*>(out + (size_t)(m + 8) * N_TOT + n) = v1;
        }
    }
}

// ------------------------------ launch -------------------------------------
extern "C" void kernel_launch(void* const* d_in, const int* in_sizes, int n_in,
                              void* d_out, int out_size) {
    const float* x = (const float*)d_in[0];      // [4,2048,2048]
    const float* w = (const float*)d_in[1];      // [8192,2048]
    float* out = (float*)d_out;                  // [4,2048,8192]

    cudaFuncSetAttribute(bitlinear_gemm,
                         cudaFuncAttributeMaxDynamicSharedMemorySize,
                         SMEM_TOTAL);

    prep_kernel<<<N_TOT + (M_TOT * K_TOT) / (256 * 8), 256>>>(x, w);

    dim3 grid(N_TOT / BN, M_TOT / BM);
    bitlinear_gemm<<<grid, 128, SMEM_TOTAL>>>(out);
}

// round 13
// speedup vs baseline: 1.0044x; 1.0044x over previous
#include <cuda_runtime.h>
#include <cuda_fp16.h>
#include <cstdint>

// ---------------------------------------------------------------------------
// BitLinear: out[m,n] = scale[n] * sum_k xh[m,k] * wq[n,k]
//   xh = fp16(x) [8192,2048], wq = ternary fp16 [8192,2048], out fp32.
//
// GEMM at the sm_103 legacy-HMMA dispatch wall (~12.9 cyc/HMMA/SMSP; five
// schedules all pin tensor=62%). This round removes the remaining non-MMA
// time: PERSISTENT kernel, grid=296 (2 CTAs/SM, fully resident), flat
// (tile,chunk) step loop with cp.async running 2 steps ahead ACROSS tile
// boundaries -> no per-tile pipeline refill, no wave-quantization tail.
// CTA 128x128, 4 warps (64x64), BK=64, 3 stages, frag double-buffering.
// ---------------------------------------------------------------------------

#define M_TOT 8192
#define N_TOT 8192
#define K_TOT 2048

#define BM 128
#define BN 128
#define BK 64
#define STAGES 3
#define CHUNKS_PER_TILE 32
#define N_TILES 4096                 // 64 x 64
#define GRID_P 296                   // 148 SMs * 2 CTAs

// smem row: 64 halves + 8 pad = 144 bytes (9 x 16B granules, odd)
#define SROWB 144
#define STILE_BYTES (BM * SROWB)     // 18432
#define SMEM_A_OFF(s) ((s) * STILE_BYTES)
#define SMEM_B_OFF(s) (STAGES * STILE_BYTES + (s) * STILE_BYTES)
#define SMEM_TOTAL (2 * STAGES * STILE_BYTES)   // 110592 -> 2 CTAs/SM

__device__ __half g_Xh[(size_t)M_TOT * K_TOT];
__device__ __half g_Wq[(size_t)N_TOT * K_TOT];
__device__ float  g_scale[N_TOT];

// ------------------------------ helpers ------------------------------------
__device__ __forceinline__ uint32_t smem_u32(const void* p) {
    uint32_t a;
    asm("{ .reg .u64 t; cvta.to.shared.u64 t, %1; cvt.u32.u64 %0, t; }"
        : "=r"(a) : "l"(p));
    return a;
}

__device__ __forceinline__ void cp_async16(uint32_t dst, const void* src) {
    asm volatile("cp.async.cg.shared.global [%0], [%1], 16;"
                 :: "r"(dst), "l"(src));
}

__device__ __forceinline__ void ldsm_x4(uint32_t addr, uint32_t* r) {
    asm volatile("ldmatrix.sync.aligned.m8n8.x4.shared.b16 {%0,%1,%2,%3}, [%4];"
                 : "=r"(r[0]), "=r"(r[1]), "=r"(r[2]), "=r"(r[3]) : "r"(addr));
}

__device__ __forceinline__ void mma16816(float* c, const uint32_t* a,
                                         uint32_t b0, uint32_t b1) {
    asm volatile(
        "mma.sync.aligned.m16n8k16.row.col.f32.f16.f16.f32 "
        "{%0,%1,%2,%3}, {%4,%5,%6,%7}, {%8,%9}, {%0,%1,%2,%3};"
        : "+f"(c[0]), "+f"(c[1]), "+f"(c[2]), "+f"(c[3])
        : "r"(a[0]), "r"(a[1]), "r"(a[2]), "r"(a[3]), "r"(b0), "r"(b1));
}

// ------------------------------ fused prep kernel --------------------------
__global__ void prep_kernel(const float* __restrict__ x,
                            const float* __restrict__ W) {
    const int b   = blockIdx.x;
    const int tid = threadIdx.x;

    if (b < N_TOT) {
        const float* wr = W + (size_t)b * K_TOT;
        const int base = tid * 8;
        float4 a = *reinterpret_cast<const float4*>(wr + base);
        float4 c = *reinterpret_cast<const float4*>(wr + base + 4);
        float s = fabsf(a.x) + fabsf(a.y) + fabsf(a.z) + fabsf(a.w) +
                  fabsf(c.x) + fabsf(c.y) + fabsf(c.z) + fabsf(c.w);
        #pragma unroll
        for (int o = 16; o; o >>= 1) s += __shfl_xor_sync(0xFFFFFFFFu, s, o);

        __shared__ float warp_s[8];
        __shared__ float s_scale;
        if ((tid & 31) == 0) warp_s[tid >> 5] = s;
        __syncthreads();
        if (tid == 0) {
            float t = 0.f;
            #pragma unroll
            for (int i = 0; i < 8; i++) t += warp_s[i];
            float sc = t * (1.0f / 2048.0f);
            if (sc < 1e-5f) sc = 1e-5f;
            g_scale[b] = sc;
            s_scale = sc;
        }
        __syncthreads();
        const float sc = s_scale;

        float v[8] = {a.x, a.y, a.z, a.w, c.x, c.y, c.z, c.w};
        __half q[8];
        #pragma unroll
        for (int i = 0; i < 8; i++) {
            float t = rintf(v[i] / sc);          // matches jnp.round
            t = fmaxf(-1.f, fminf(1.f, t));
            q[i] = __float2half_rn(t);
        }
        *reinterpret_cast<uint4*>(g_Wq + (size_t)b * K_TOT + base) =
            *reinterpret_cast<uint4*>(q);
    } else {
        size_t i = (size_t)(b - N_TOT) * 256 + tid;
        const float4* X4 = reinterpret_cast<const float4*>(x);
        float4 a = X4[2 * i];
        float4 c = X4[2 * i + 1];
        __half2 h0 = __floats2half2_rn(a.x, a.y);
        __half2 h1 = __floats2half2_rn(a.z, a.w);
        __half2 h2 = __floats2half2_rn(c.x, c.y);
        __half2 h3 = __floats2half2_rn(c.z, c.w);
        uint4 o;
        o.x = *reinterpret_cast<uint32_t*>(&h0);
        o.y = *reinterpret_cast<uint32_t*>(&h1);
        o.z = *reinterpret_cast<uint32_t*>(&h2);
        o.w = *reinterpret_cast<uint32_t*>(&h3);
        reinterpret_cast<uint4*>(g_Xh)[i] = o;
    }
}

// ------------------------------ GEMM kernel (persistent) -------------------
__global__ void __launch_bounds__(128, 2)
bitlinear_gemm(float* __restrict__ out) {
    extern __shared__ char smem[];
    const uint32_t sbase = smem_u32(smem);
    const int tid    = threadIdx.x;
    const int wid    = tid >> 5;
    const int lane   = tid & 31;
    const int warp_m = wid & 1;       // 2 warps along M (64 each)
    const int warp_n = wid >> 1;      // 2 warps along N (64 each)
    const int bid = blockIdx.x;

    // this CTA's flat step count: tiles bid, bid+296, ... < 4096
    const int ntiles = (N_TILES - bid + GRID_P - 1) / GRID_P;
    const int S = ntiles * CHUNKS_PER_TILE;

    // step -> tile m0/n0 (n fastest, matches 64x64 tiling)
    auto tile_mn = [&](int step, int& tm0, int& tn0) {
        int gidx = bid + (step >> 5) * GRID_P;
        tn0 = (gidx & 63) * BN;
        tm0 = (gidx >> 6) * BM;
    };

    // copy for step: A/B each 128 rows x 8 segs(16B); 8 pairs per thread
    auto issue_copy = [&](int stage, int step) {
        int tm0, tn0;
        tile_mn(step, tm0, tn0);
        const int k0 = (step & 31) * BK;
        const __half* Ag = g_Xh + (size_t)tm0 * K_TOT + k0;
        const __half* Bg = g_Wq + (size_t)tn0 * K_TOT + k0;
        uint32_t da = sbase + SMEM_A_OFF(stage);
        uint32_t db = sbase + SMEM_B_OFF(stage);
        #pragma unroll
        for (int j = 0; j < 8; j++) {
            int s = tid + 128 * j;
            int row = s >> 3, sg = s & 7;
            uint32_t off = row * SROWB + sg * 16;
            cp_async16(da + off, Ag + (size_t)row * K_TOT + sg * 8);
            cp_async16(db + off, Bg + (size_t)row * K_TOT + sg * 8);
        }
    };

    // ldmatrix per-thread address components
    const int aRow = warp_m * 64 + (lane & 15);        // + mt*16
    const int aCol = (lane >> 4) * 8;                  // + ks*16
    const int g    = lane >> 3;
    const int bRow = warp_n * 64 + ((g >> 1) << 3) + (lane & 7);  // + nt*16
    const int bCol = (g & 1) * 8;                      // + ks*16

    float acc[4][8][4];
    #pragma unroll
    for (int i = 0; i < 4; i++)
        #pragma unroll
        for (int j = 0; j < 8; j++)
            #pragma unroll
            for (int t = 0; t < 4; t++) acc[i][j][t] = 0.f;

    uint32_t af[2][4][4];
    uint32_t bf[2][4][4];

    auto load_frags = [&](uint32_t sa, uint32_t sb, int ks, int buf) {
        #pragma unroll
        for (int mt = 0; mt < 4; mt++)
            ldsm_x4(sa + (aRow + mt * 16) * SROWB + (aCol + ks * 16) * 2,
                    af[buf][mt]);
        #pragma unroll
        for (int nt = 0; nt < 4; nt++)
            ldsm_x4(sb + (bRow + nt * 16) * SROWB + (bCol + ks * 16) * 2,
                    bf[buf][nt]);
    };
    auto do_mma = [&](int buf) {
        #pragma unroll
        for (int mi = 0; mi < 4; mi++)
            #pragma unroll
            for (int ni = 0; ni < 8; ni++)
                mma16816(acc[mi][ni], af[buf][mi],
                         bf[buf][ni >> 1][(ni & 1) * 2],
                         bf[buf][ni >> 1][(ni & 1) * 2 + 1]);
    };

    // global prologue: steps 0,1 (pipeline never refills after this)
    issue_copy(0, 0);
    asm volatile("cp.async.commit_group;");
    if (S > 1) issue_copy(1, 1);
    asm volatile("cp.async.commit_group;");

    #pragma unroll 1
    for (int s = 0; s < S; s++) {
        asm volatile("cp.async.wait_group %0;" :: "n"(STAGES - 2));
        __syncthreads();

        const int ns = s + 2;
        if (ns < S) issue_copy(ns % STAGES, ns);
        asm volatile("cp.async.commit_group;");

        const int st = s % STAGES;
        const uint32_t sa = sbase + SMEM_A_OFF(st);
        const uint32_t sb = sbase + SMEM_B_OFF(st);

        // software-pipelined ks loop: LDSM(ks+1) before MMA(ks)
        load_frags(sa, sb, 0, 0);
        #pragma unroll
        for (int ks = 0; ks < 4; ks++) {
            const int cur = ks & 1;
            if (ks < 3) load_frags(sa, sb, ks + 1, cur ^ 1);
            do_mma(cur);
        }

        // ---- tile finished? epilogue + acc reset (copies already ahead) ----
        if ((s & 31) == 31) {
            int m0, n0;
            tile_mn(s, m0, n0);
            const int q = lane >> 2;
            const int t = lane & 3;
            #pragma unroll
            for (int ni = 0; ni < 8; ni++) {
                const int n = n0 + warp_n * 64 + ni * 8 + t * 2;
                const float2 sc =
                    *reinterpret_cast<const float2*>(&g_scale[n]);
                #pragma unroll
                for (int mi = 0; mi < 4; mi++) {
                    const int m = m0 + warp_m * 64 + mi * 16 + q;
                    float2 v0 = make_float2(acc[mi][ni][0] * sc.x,
                                            acc[mi][ni][1] * sc.y);
                    float2 v1 = make_float2(acc[mi][ni][2] * sc.x,
                                            acc[mi][ni][3] * sc.y);
                    *reinterpret_cast<float2*>(out + (size_t)m * N_TOT + n) = v0;
                    *reinterpret_cast<float2*>(out + (size_t)(m + 8) * N_TOT + n) = v1;
                    acc[mi][ni][0] = 0.f; acc[mi][ni][1] = 0.f;
                    acc[mi][ni][2] = 0.f; acc[mi][ni][3] = 0.f;
                }
            }
        }
    }
}

// ------------------------------ launch -------------------------------------
extern "C" void kernel_launch(void* const* d_in, const int* in_sizes, int n_in,
                              void* d_out, int out_size) {
    const float* x = (const float*)d_in[0];      // [4,2048,2048]
    const float* w = (const float*)d_in[1];      // [8192,2048]
    float* out = (float*)d_out;                  // [4,2048,8192]

    cudaFuncSetAttribute(bitlinear_gemm,
                         cudaFuncAttributeMaxDynamicSharedMemorySize,
                         SMEM_TOTAL);

    prep_kernel<<<N_TOT + (M_TOT * K_TOT) / (256 * 8), 256>>>(x, w);

    bitlinear_gemm<<<GRID_P, 128, SMEM_TOTAL>>>(out);
}